// round 5
// baseline (speedup 1.0000x reference)
#include <cuda_runtime.h>
#include <cuda_bf16.h>
#include <cstdint>

// Fixed problem shape: N=100000, E=1250000, IN=6, HID=64.
#define NMAX 100352
#define EMAX 1310720
#define HID 64

// ---------------- scratch (device globals; 16B aligned for float4) ----------------
__device__ __align__(16) float  g_dis [NMAX];
__device__ __align__(16) float  g_w   [NMAX];       // w[src] = sum over out-edges of dis[dst]
__device__ __align__(16) float  g_hs  [NMAX * HID]; // dis-scaled layer-1 pre-agg features
__device__ __align__(16) float  g_h   [NMAX * HID]; // post layer-1 activations
__device__ __align__(16) double g_u   [HID];        // weighted row-sum of g_h
__device__ int g_degi[NMAX];
__device__ int g_off [NMAX + 1];
__device__ int g_cur [NMAX];
__device__ int g_bsum[128];
__device__ int g_boff[128];
__device__ int g_csrc[EMAX];                        // CSR: src ids grouped by dst
__device__ int g_is64;

// ---------------- zero + dtype detect ----------------
// int64 little-endian edge data viewed as int32 has every odd word == 0.
__global__ void zero_kernel(const int* __restrict__ ei32, int n) {
    int i = blockIdx.x * blockDim.x + threadIdx.x;
    if (i < n)  { g_degi[i] = 0; g_w[i] = 0.0f; }
    if (i < HID) g_u[i] = 0.0;
    if (i == 0) {
        int is64 = 1;
        for (int k = 1; k < 128; k += 2)
            if (ei32[k] != 0) { is64 = 0; break; }
        g_is64 = is64;
    }
}

// ---------------- degree count ----------------
__global__ void degcnt_kernel(const int* __restrict__ ei32, int E) {
    int e = blockIdx.x * blockDim.x + threadIdx.x;
    if (e < E) {
        int dst = g_is64 ? __ldg(&ei32[2 * (E + e)]) : __ldg(&ei32[E + e]);
        atomicAdd(&g_degi[dst], 1);
    }
}

// ---------------- 3-stage exclusive scan (tile = 1024) ----------------
__global__ void scanA_kernel(int n) {
    __shared__ int s[1024];
    int t = threadIdx.x;
    int i = blockIdx.x * 1024 + t;
    s[t] = (i < n) ? g_degi[i] : 0;
    __syncthreads();
    for (int o = 512; o; o >>= 1) {
        if (t < o) s[t] += s[t + o];
        __syncthreads();
    }
    if (t == 0) g_bsum[blockIdx.x] = s[0];
}

__global__ void scanB_kernel(int nb, int n) {
    __shared__ int s[2][128];
    int t = threadIdx.x;                // 128 threads
    int v = (t < nb) ? g_bsum[t] : 0;
    s[0][t] = v;
    __syncthreads();
    int cur = 0;
    for (int o = 1; o < 128; o <<= 1) {
        int nxt = cur ^ 1;
        s[nxt][t] = s[cur][t] + ((t >= o) ? s[cur][t - o] : 0);
        __syncthreads();
        cur = nxt;
    }
    if (t < nb) g_boff[t] = s[cur][t] - v;     // exclusive
    if (t == 127) g_off[n] = s[cur][127];      // total edge count
}

__global__ void scanC_kernel(int n) {
    __shared__ int s[2][1024];
    int t = threadIdx.x;
    int i = blockIdx.x * 1024 + t;
    int v = (i < n) ? g_degi[i] : 0;
    s[0][t] = v;
    __syncthreads();
    int cur = 0;
    for (int o = 1; o < 1024; o <<= 1) {
        int nxt = cur ^ 1;
        s[nxt][t] = s[cur][t] + ((t >= o) ? s[cur][t - o] : 0);
        __syncthreads();
        cur = nxt;
    }
    if (i < n) {
        int off = g_boff[blockIdx.x] + s[cur][t] - v;   // exclusive
        g_off[i] = off;
        g_cur[i] = off;
        g_dis[i] = rsqrtf((float)v + 1.0f);             // fused dis
    }
}

// ---------------- CSR fill + w scatter ----------------
__global__ void fill_kernel(const int* __restrict__ ei32, int E) {
    int e = blockIdx.x * blockDim.x + threadIdx.x;
    if (e < E) {
        int src, dst;
        if (g_is64) { src = __ldg(&ei32[2 * e]); dst = __ldg(&ei32[2 * (E + e)]); }
        else        { src = __ldg(&ei32[e]);     dst = __ldg(&ei32[E + e]); }
        int p = atomicAdd(&g_cur[dst], 1);
        g_csrc[p] = src;
        atomicAdd(&g_w[src], __ldg(&g_dis[dst]));
    }
}

// ---------------- layer-1 GEMM (K=6): hs = (x @ W1) * dis ----------------
__global__ void h1_kernel(const float* __restrict__ x, const float* __restrict__ W1, int n) {
    __shared__ float sW[6 * HID];
    __shared__ float sx[4 * 6];
    int tid = threadIdx.x;
    // FIX: 6*HID = 384 > blockDim (256) — must stride-loop, else sW[256..383]
    // is uninitialized shared memory (the Round 2-4 latent bug).
    for (int i = tid; i < 6 * HID; i += 256) sW[i] = W1[i];
    int base = blockIdx.x * 4;
    if (tid < 24) {
        int r = tid / 6, c = tid % 6;
        sx[tid] = (base + r < n) ? x[(size_t)(base + r) * 6 + c] : 0.0f;
    }
    __syncthreads();
    int j = tid & 63, nl = tid >> 6;
    int row = base + nl;
    if (row < n) {
        float acc = 0.0f;
#pragma unroll
        for (int k = 0; k < 6; ++k) acc += sx[nl * 6 + k] * sW[k * HID + j];
        g_hs[(size_t)row * HID + j] = acc * g_dis[row];
    }
}

// ---------------- pull aggregation (layer 1 only): 16 threads per dst ----------------
// g_h[dst] = relu( dis[dst]*(self + sum_{src->dst} hs[src]) + b1 )
__global__ void pull_kernel(const float* __restrict__ bias, int n) {
    int grp  = blockIdx.x * 16 + (threadIdx.x >> 4);
    int lane = threadIdx.x & 15;
    if (grp >= n) return;
    const float4* rowp = (const float4*)g_hs;
    float4 acc = __ldg(rowp + (size_t)grp * 16 + lane);          // self-loop
    int k = g_off[grp], e = g_off[grp + 1];
    for (; k + 4 <= e; k += 4) {
        int s0 = __ldg(&g_csrc[k]);
        int s1 = __ldg(&g_csrc[k + 1]);
        int s2 = __ldg(&g_csrc[k + 2]);
        int s3 = __ldg(&g_csrc[k + 3]);
        float4 v0 = __ldg(rowp + (size_t)s0 * 16 + lane);
        float4 v1 = __ldg(rowp + (size_t)s1 * 16 + lane);
        float4 v2 = __ldg(rowp + (size_t)s2 * 16 + lane);
        float4 v3 = __ldg(rowp + (size_t)s3 * 16 + lane);
        acc.x += (v0.x + v1.x) + (v2.x + v3.x);
        acc.y += (v0.y + v1.y) + (v2.y + v3.y);
        acc.z += (v0.z + v1.z) + (v2.z + v3.z);
        acc.w += (v0.w + v1.w) + (v2.w + v3.w);
    }
    for (; k < e; ++k) {
        int s0 = __ldg(&g_csrc[k]);
        float4 v = __ldg(rowp + (size_t)s0 * 16 + lane);
        acc.x += v.x; acc.y += v.y; acc.z += v.z; acc.w += v.w;
    }
    float d = g_dis[grp];
    float4 b = __ldg((const float4*)bias + lane);
    float4 o;
    o.x = fmaxf(fmaf(acc.x, d, b.x), 0.f);
    o.y = fmaxf(fmaf(acc.y, d, b.y), 0.f);
    o.z = fmaxf(fmaf(acc.z, d, b.z), 0.f);
    o.w = fmaxf(fmaf(acc.w, d, b.w), 0.f);
    ((float4*)g_h)[(size_t)grp * 16 + lane] = o;
}

// ---------------- u = sum_i c[i] * g_h[i,:],  c[i] = dis[i]*(w[i]+dis[i]) ----------------
__global__ void reduceu_kernel(int n) {
    __shared__ double s[256];
    int tid = threadIdx.x;
    int j  = tid & 63;
    int rw = tid >> 6;   // 0..3
    double acc = 0.0;
    for (int i = blockIdx.x * 4 + rw; i < n; i += gridDim.x * 4) {
        float d = g_dis[i];
        double c = (double)d * ((double)g_w[i] + (double)d);
        acc += c * (double)g_h[(size_t)i * HID + j];
    }
    s[tid] = acc;
    __syncthreads();
    if (tid < 64) {
        double v = (s[tid] + s[tid + 64]) + (s[tid + 128] + s[tid + 192]);
        atomicAdd(&g_u[tid], v);
    }
}

// ---------------- final: sigmoid( ((u @ W2)/n + b2) . Wfc + bfc ) ----------------
__global__ void final_kernel(const float* __restrict__ W2, const float* __restrict__ b2,
                             const float* __restrict__ Wfc, const float* __restrict__ bfc,
                             float* __restrict__ out, int n) {
    __shared__ double s[HID];
    int j = threadIdx.x;   // 64 threads
    double acc = 0.0;
#pragma unroll 8
    for (int k = 0; k < HID; ++k)
        acc += g_u[k] * (double)W2[k * HID + j];
    double t = acc / (double)n + (double)b2[j];
    s[j] = t * (double)Wfc[j];
    __syncthreads();
    if (j < 32) {
        double v = s[j] + s[j + 32];
#pragma unroll
        for (int o = 16; o; o >>= 1) v += __shfl_down_sync(0xffffffff, v, o);
        if (j == 0) {
            double z = v + (double)bfc[0];
            out[0] = (float)(1.0 / (1.0 + exp(-z)));
        }
    }
}

// ================================================================ launch
extern "C" void kernel_launch(void* const* d_in, const int* in_sizes, int n_in,
                              void* d_out, int out_size) {
    const float* x   = (const float*)d_in[0];
    const int*   ei  = (const int*)d_in[1];   // int32 OR int64 (auto-detected on device)
    const float* W1  = (const float*)d_in[2];
    const float* b1  = (const float*)d_in[3];
    const float* W2  = (const float*)d_in[4];
    const float* b2  = (const float*)d_in[5];
    const float* Wfc = (const float*)d_in[6];
    const float* bfc = (const float*)d_in[7];
    float* out = (float*)d_out;

    int n = in_sizes[0] / 6;      // 100000
    int E = in_sizes[1] / 2;      // 1250000
    int nb = (n + 1023) / 1024;   // scan tiles (<=98)

    zero_kernel<<<(n + 255) / 256, 256>>>(ei, n);
    degcnt_kernel<<<(E + 255) / 256, 256>>>(ei, E);
    scanA_kernel<<<nb, 1024>>>(n);
    scanB_kernel<<<1, 128>>>(nb, n);
    scanC_kernel<<<nb, 1024>>>(n);
    fill_kernel<<<(E + 255) / 256, 256>>>(ei, E);

    h1_kernel<<<(n + 3) / 4, 256>>>(x, W1, n);
    pull_kernel<<<(n + 15) / 16, 256>>>(b1, n);

    reduceu_kernel<<<512, 256>>>(n);
    final_kernel<<<1, HID>>>(W2, b2, Wfc, bfc, out, n);
}

// round 6
// speedup vs baseline: 1.6544x; 1.6544x over previous
#include <cuda_runtime.h>
#include <cuda_bf16.h>
#include <cstdint>

// Fixed problem shape: N=100000, E=1250000, IN=6, HID=64.
#define NMAX 100352
#define EMAX 1310720
#define HID 64

// ---------------- scratch (device globals; 16B aligned) ----------------
__device__ __align__(16) float  g_dis [NMAX];
__device__ __align__(16) float  g_w   [NMAX];        // w[src] = sum over out-edges of dis[dst]
__device__ __align__(16) __nv_bfloat16 g_hsb[NMAX * HID];  // dis-scaled layer-1 features (bf16)
__device__ __align__(16) double g_u   [HID];         // weighted row-sum of layer-1 activations
__device__ int g_degi[NMAX];
__device__ int g_off [NMAX + 1];
__device__ int g_cur [NMAX];
__device__ int g_bsum[128];
__device__ int g_boff[128];
__device__ int g_csrc[EMAX];                         // CSR: src ids grouped by dst
__device__ int g_is64;

// ---------------- zero + dtype detect ----------------
// int64 little-endian edge data viewed as int32 has every odd word == 0.
__global__ void zero_kernel(const int* __restrict__ ei32, int n) {
    int i = blockIdx.x * blockDim.x + threadIdx.x;
    if (i < n)  { g_degi[i] = 0; g_w[i] = 0.0f; }
    if (i < HID) g_u[i] = 0.0;
    if (i == 0) {
        int is64 = 1;
        for (int k = 1; k < 128; k += 2)
            if (ei32[k] != 0) { is64 = 0; break; }
        g_is64 = is64;
    }
}

// ---------------- degree count ----------------
__global__ void degcnt_kernel(const int* __restrict__ ei32, int E) {
    int e = blockIdx.x * blockDim.x + threadIdx.x;
    if (e < E) {
        int dst = g_is64 ? __ldg(&ei32[2 * (E + e)]) : __ldg(&ei32[E + e]);
        atomicAdd(&g_degi[dst], 1);
    }
}

// ---------------- 3-stage exclusive scan (tile = 1024) ----------------
__global__ void scanA_kernel(int n) {
    __shared__ int s[1024];
    int t = threadIdx.x;
    int i = blockIdx.x * 1024 + t;
    s[t] = (i < n) ? g_degi[i] : 0;
    __syncthreads();
    for (int o = 512; o; o >>= 1) {
        if (t < o) s[t] += s[t + o];
        __syncthreads();
    }
    if (t == 0) g_bsum[blockIdx.x] = s[0];
}

__global__ void scanB_kernel(int nb, int n) {
    __shared__ int s[2][128];
    int t = threadIdx.x;                // 128 threads
    int v = (t < nb) ? g_bsum[t] : 0;
    s[0][t] = v;
    __syncthreads();
    int cur = 0;
    for (int o = 1; o < 128; o <<= 1) {
        int nxt = cur ^ 1;
        s[nxt][t] = s[cur][t] + ((t >= o) ? s[cur][t - o] : 0);
        __syncthreads();
        cur = nxt;
    }
    if (t < nb) g_boff[t] = s[cur][t] - v;     // exclusive
    if (t == 127) g_off[n] = s[cur][127];      // total edge count
}

__global__ void scanC_kernel(int n) {
    __shared__ int s[2][1024];
    int t = threadIdx.x;
    int i = blockIdx.x * 1024 + t;
    int v = (i < n) ? g_degi[i] : 0;
    s[0][t] = v;
    __syncthreads();
    int cur = 0;
    for (int o = 1; o < 1024; o <<= 1) {
        int nxt = cur ^ 1;
        s[nxt][t] = s[cur][t] + ((t >= o) ? s[cur][t - o] : 0);
        __syncthreads();
        cur = nxt;
    }
    if (i < n) {
        int off = g_boff[blockIdx.x] + s[cur][t] - v;   // exclusive
        g_off[i] = off;
        g_cur[i] = off;
        g_dis[i] = rsqrtf((float)v + 1.0f);             // fused dis
    }
}

// ---------------- CSR fill + w scatter ----------------
__global__ void fill_kernel(const int* __restrict__ ei32, int E) {
    int e = blockIdx.x * blockDim.x + threadIdx.x;
    if (e < E) {
        int src, dst;
        if (g_is64) { src = __ldg(&ei32[2 * e]); dst = __ldg(&ei32[2 * (E + e)]); }
        else        { src = __ldg(&ei32[e]);     dst = __ldg(&ei32[E + e]); }
        int p = atomicAdd(&g_cur[dst], 1);
        g_csrc[p] = src;
        atomicAdd(&g_w[src], __ldg(&g_dis[dst]));
    }
}

// ---------------- layer-1 GEMM (K=6): hsb = bf16( (x @ W1) * dis ) ----------------
__global__ void h1_kernel(const float* __restrict__ x, const float* __restrict__ W1, int n) {
    __shared__ float sW[6 * HID];
    __shared__ float sx[4 * 6];
    int tid = threadIdx.x;
    for (int i = tid; i < 6 * HID; i += 256) sW[i] = W1[i];   // stride loop (384 > 256)
    int base = blockIdx.x * 4;
    if (tid < 24) {
        int r = tid / 6, c = tid % 6;
        sx[tid] = (base + r < n) ? x[(size_t)(base + r) * 6 + c] : 0.0f;
    }
    __syncthreads();
    int j = tid & 63, nl = tid >> 6;
    int row = base + nl;
    if (row < n) {
        float acc = 0.0f;
#pragma unroll
        for (int k = 0; k < 6; ++k) acc += sx[nl * 6 + k] * sW[k * HID + j];
        g_hsb[(size_t)row * HID + j] = __float2bfloat16(acc * g_dis[row]);
    }
}

// ---------------- bf16 unpack helpers ----------------
__device__ __forceinline__ void bf16x8_add(float* acc, uint4 v) {
    float2 p;
    p = __bfloat1622float2(*reinterpret_cast<const __nv_bfloat162*>(&v.x)); acc[0] += p.x; acc[1] += p.y;
    p = __bfloat1622float2(*reinterpret_cast<const __nv_bfloat162*>(&v.y)); acc[2] += p.x; acc[3] += p.y;
    p = __bfloat1622float2(*reinterpret_cast<const __nv_bfloat162*>(&v.z)); acc[4] += p.x; acc[5] += p.y;
    p = __bfloat1622float2(*reinterpret_cast<const __nv_bfloat162*>(&v.w)); acc[6] += p.x; acc[7] += p.y;
}

// ---------------- fused pull + relu + weighted readout ----------------
// 8 threads per dst (lane owns 8 columns). For each dst:
//   val = relu( dis*(self + sum_src hs[src]) + b1 );  u += dis*(w+dis) * val
// Per-thread float partials -> block shared reduce -> double atomicAdd into g_u.
__global__ void pull_kernel(const float* __restrict__ bias, int n) {
    __shared__ float sred[32 * 65];
    int tid = threadIdx.x;                 // 256
    int tg  = tid >> 3;                    // group in block: 0..31
    int l   = tid & 7;                     // lane in group: 0..7
    float b[8];
#pragma unroll
    for (int c = 0; c < 8; ++c) b[c] = __ldg(&bias[l * 8 + c]);
    float uacc[8] = {};
    const uint4* rowp = (const uint4*)g_hsb;   // 8 x uint4 per row
    int stride = gridDim.x * 32;
    for (int grp = blockIdx.x * 32 + tg; grp < n; grp += stride) {
        float acc[8] = {};
        uint4 vs = __ldg(rowp + (size_t)grp * 8 + l);   // self-loop
        bf16x8_add(acc, vs);
        int k = __ldg(&g_off[grp]), e = __ldg(&g_off[grp + 1]);
        for (; k + 2 <= e; k += 2) {
            int s0 = __ldg(&g_csrc[k]);
            int s1 = __ldg(&g_csrc[k + 1]);
            uint4 v0 = __ldg(rowp + (size_t)s0 * 8 + l);
            uint4 v1 = __ldg(rowp + (size_t)s1 * 8 + l);
            bf16x8_add(acc, v0);
            bf16x8_add(acc, v1);
        }
        if (k < e) {
            int s0 = __ldg(&g_csrc[k]);
            uint4 v0 = __ldg(rowp + (size_t)s0 * 8 + l);
            bf16x8_add(acc, v0);
        }
        float d  = __ldg(&g_dis[grp]);
        float cw = d * (__ldg(&g_w[grp]) + d);
#pragma unroll
        for (int c = 0; c < 8; ++c) {
            float val = fmaxf(fmaf(acc[c], d, b[c]), 0.f);
            uacc[c] = fmaf(cw, val, uacc[c]);
        }
    }
#pragma unroll
    for (int c = 0; c < 8; ++c) sred[tg * 65 + l * 8 + c] = uacc[c];
    __syncthreads();
    if (tid < HID) {
        double s = 0.0;
#pragma unroll
        for (int g = 0; g < 32; ++g) s += (double)sred[g * 65 + tid];
        atomicAdd(&g_u[tid], s);
    }
}

// ---------------- final: sigmoid( ((u @ W2)/n + b2) . Wfc + bfc ) ----------------
__global__ void final_kernel(const float* __restrict__ W2, const float* __restrict__ b2,
                             const float* __restrict__ Wfc, const float* __restrict__ bfc,
                             float* __restrict__ out, int n) {
    __shared__ double s[HID];
    int j = threadIdx.x;   // 64 threads
    double acc = 0.0;
#pragma unroll 8
    for (int k = 0; k < HID; ++k)
        acc += g_u[k] * (double)W2[k * HID + j];
    double t = acc / (double)n + (double)b2[j];
    s[j] = t * (double)Wfc[j];
    __syncthreads();
    if (j < 32) {
        double v = s[j] + s[j + 32];
#pragma unroll
        for (int o = 16; o; o >>= 1) v += __shfl_down_sync(0xffffffff, v, o);
        if (j == 0) {
            double z = v + (double)bfc[0];
            out[0] = (float)(1.0 / (1.0 + exp(-z)));
        }
    }
}

// ================================================================ launch
extern "C" void kernel_launch(void* const* d_in, const int* in_sizes, int n_in,
                              void* d_out, int out_size) {
    const float* x   = (const float*)d_in[0];
    const int*   ei  = (const int*)d_in[1];   // int32 OR int64 (auto-detected on device)
    const float* W1  = (const float*)d_in[2];
    const float* b1  = (const float*)d_in[3];
    const float* W2  = (const float*)d_in[4];
    const float* b2  = (const float*)d_in[5];
    const float* Wfc = (const float*)d_in[6];
    const float* bfc = (const float*)d_in[7];
    float* out = (float*)d_out;

    int n = in_sizes[0] / 6;      // 100000
    int E = in_sizes[1] / 2;      // 1250000
    int nb = (n + 1023) / 1024;   // scan tiles (<=98)

    zero_kernel<<<(n + 255) / 256, 256>>>(ei, n);
    degcnt_kernel<<<(E + 255) / 256, 256>>>(ei, E);
    scanA_kernel<<<nb, 1024>>>(n);
    scanB_kernel<<<1, 128>>>(nb, n);
    scanC_kernel<<<nb, 1024>>>(n);
    fill_kernel<<<(E + 255) / 256, 256>>>(ei, E);

    h1_kernel<<<(n + 3) / 4, 256>>>(x, W1, n);

    int ngrpblocks = 1024;        // 32 dst-groups per block, grid-stride
    pull_kernel<<<ngrpblocks, 256>>>(b1, n);

    final_kernel<<<1, HID>>>(W2, b2, Wfc, bfc, out, n);
}

// round 7
// speedup vs baseline: 2.5119x; 1.5183x over previous
#include <cuda_runtime.h>
#include <cuda_bf16.h>
#include <cstdint>

// Fixed problem shape: N=100000, E=1250000, IN=6, HID=64.
#define NMAX 100352
#define HID 64

// ---------------- scratch (device globals; 16B aligned) ----------------
__device__ __align__(16) float  g_dis [NMAX];
__device__ __align__(16) float  g_w   [NMAX];       // w[src] = sum over out-edges of dis[dst]
__device__ __align__(16) float  g_xs  [NMAX * 8];   // dis-scaled raw features, padded 6->8
__device__ __align__(16) float  g_agg [NMAX * 8];   // edge-aggregated xs (padded)
__device__ __align__(16) double g_u   [HID];        // weighted readout accumulator
__device__ int g_degi[NMAX];
__device__ int g_is64;

// ---------------- zero + dtype detect ----------------
// int64 little-endian edge data viewed as int32 has every odd word == 0.
__global__ void zero_kernel(const int* __restrict__ ei32, int n) {
    int i = blockIdx.x * blockDim.x + threadIdx.x;
    if (i < n)   g_degi[i] = 0;
    if (i < HID) g_u[i] = 0.0;
    if (i == 0) {
        int is64 = 1;
        for (int k = 1; k < 128; k += 2)
            if (ei32[k] != 0) { is64 = 0; break; }
        g_is64 = is64;
    }
}

// ---------------- degree count ----------------
__global__ void degcnt_kernel(const int* __restrict__ ei32, int E) {
    int e = blockIdx.x * blockDim.x + threadIdx.x;
    if (e < E) {
        int dst = g_is64 ? __ldg(&ei32[2 * (E + e)]) : __ldg(&ei32[E + e]);
        atomicAdd(&g_degi[dst], 1);
    }
}

// ---------------- prep: dis, xs = x*dis (padded), agg = 0, w = 0 ----------------
__global__ void prep_kernel(const float* __restrict__ x, int n) {
    int i = blockIdx.x * blockDim.x + threadIdx.x;
    if (i >= n) return;
    float d = rsqrtf((float)g_degi[i] + 1.0f);
    g_dis[i] = d;
    g_w[i]   = 0.0f;
    const float* xi = x + (size_t)i * 6;
    float4 a, b;
    a.x = xi[0] * d;  a.y = xi[1] * d;  a.z = xi[2] * d;  a.w = xi[3] * d;
    b.x = xi[4] * d;  b.y = xi[5] * d;  b.z = 0.0f;       b.w = 0.0f;
    ((float4*)g_xs )[i * 2]     = a;
    ((float4*)g_xs )[i * 2 + 1] = b;
    ((float4*)g_agg)[i * 2]     = make_float4(0.f, 0.f, 0.f, 0.f);
    ((float4*)g_agg)[i * 2 + 1] = make_float4(0.f, 0.f, 0.f, 0.f);
}

// ---------------- edge scatter: agg[dst] += xs[src] (6 dims), w[src] += dis[dst] ----------------
__global__ void scatter_kernel(const int* __restrict__ ei32, int E) {
    int e = blockIdx.x * blockDim.x + threadIdx.x;
    if (e >= E) return;
    int src, dst;
    if (g_is64) { src = __ldg(&ei32[2 * e]); dst = __ldg(&ei32[2 * (E + e)]); }
    else        { src = __ldg(&ei32[e]);     dst = __ldg(&ei32[E + e]); }
    const float4* sp = (const float4*)g_xs;
    float4 v0 = __ldg(sp + (size_t)src * 2);
    float4 v1 = __ldg(sp + (size_t)src * 2 + 1);   // lanes 6,7 are zero
    float* p = g_agg + (size_t)dst * 8;
    asm volatile("red.global.add.v4.f32 [%0], {%1,%2,%3,%4};"
                 :: "l"(p), "f"(v0.x), "f"(v0.y), "f"(v0.z), "f"(v0.w) : "memory");
    asm volatile("red.global.add.v4.f32 [%0], {%1,%2,%3,%4};"
                 :: "l"(p + 4), "f"(v1.x), "f"(v1.y), "f"(v1.z), "f"(v1.w) : "memory");
    atomicAdd(&g_w[src], __ldg(&g_dis[dst]));
}

// ---------------- u[j] = sum_i c[i] * relu( (dis[i]*(agg[i]+xs[i])) . W1[:,j] + b1[j] ) ----------
// c[i] = dis[i]*(w[i]+dis[i]).  256 threads = 4 row-lanes x 64 columns.
__global__ void u_kernel(const float* __restrict__ W1, const float* __restrict__ b1, int n) {
    __shared__ float sW[6 * HID];
    __shared__ float sred[256];
    int tid = threadIdx.x;
    for (int i = tid; i < 6 * HID; i += 256) sW[i] = W1[i];
    __syncthreads();
    int j  = tid & 63;
    int rw = tid >> 6;     // 0..3
    float bj = __ldg(&b1[j]);
    float w0 = sW[0 * HID + j], w1 = sW[1 * HID + j], w2 = sW[2 * HID + j];
    float w3 = sW[3 * HID + j], w4 = sW[4 * HID + j], w5 = sW[5 * HID + j];
    float uacc = 0.0f;
    for (int i = blockIdx.x * 4 + rw; i < n; i += gridDim.x * 4) {
        float d = __ldg(&g_dis[i]);
        const float4* ap = (const float4*)(g_agg + (size_t)i * 8);
        const float4* xp = (const float4*)(g_xs  + (size_t)i * 8);
        float4 a0 = __ldg(ap), a1 = __ldg(ap + 1);
        float4 x0 = __ldg(xp), x1 = __ldg(xp + 1);
        float v0 = (a0.x + x0.x) * d, v1 = (a0.y + x0.y) * d, v2 = (a0.z + x0.z) * d;
        float v3 = (a0.w + x0.w) * d, v4 = (a1.x + x1.x) * d, v5 = (a1.y + x1.y) * d;
        float h = bj;
        h = fmaf(v0, w0, h); h = fmaf(v1, w1, h); h = fmaf(v2, w2, h);
        h = fmaf(v3, w3, h); h = fmaf(v4, w4, h); h = fmaf(v5, w5, h);
        h = fmaxf(h, 0.0f);
        float c = d * (__ldg(&g_w[i]) + d);
        uacc = fmaf(c, h, uacc);
    }
    sred[tid] = uacc;
    __syncthreads();
    if (tid < HID) {
        double s = (double)sred[tid] + (double)sred[tid + 64]
                 + (double)sred[tid + 128] + (double)sred[tid + 192];
        atomicAdd(&g_u[tid], s);
    }
}

// ---------------- final: sigmoid( ((u @ W2)/n + b2) . Wfc + bfc ) ----------------
__global__ void final_kernel(const float* __restrict__ W2, const float* __restrict__ b2,
                             const float* __restrict__ Wfc, const float* __restrict__ bfc,
                             float* __restrict__ out, int n) {
    __shared__ double s[HID];
    int j = threadIdx.x;   // 64 threads
    double acc = 0.0;
#pragma unroll 8
    for (int k = 0; k < HID; ++k)
        acc += g_u[k] * (double)W2[k * HID + j];
    double t = acc / (double)n + (double)b2[j];
    s[j] = t * (double)Wfc[j];
    __syncthreads();
    if (j < 32) {
        double v = s[j] + s[j + 32];
#pragma unroll
        for (int o = 16; o; o >>= 1) v += __shfl_down_sync(0xffffffff, v, o);
        if (j == 0) {
            double z = v + (double)bfc[0];
            out[0] = (float)(1.0 / (1.0 + exp(-z)));
        }
    }
}

// ================================================================ launch
extern "C" void kernel_launch(void* const* d_in, const int* in_sizes, int n_in,
                              void* d_out, int out_size) {
    const float* x   = (const float*)d_in[0];
    const int*   ei  = (const int*)d_in[1];   // int32 OR int64 (auto-detected on device)
    const float* W1  = (const float*)d_in[2];
    const float* b1  = (const float*)d_in[3];
    const float* W2  = (const float*)d_in[4];
    const float* b2  = (const float*)d_in[5];
    const float* Wfc = (const float*)d_in[6];
    const float* bfc = (const float*)d_in[7];
    float* out = (float*)d_out;

    int n = in_sizes[0] / 6;      // 100000
    int E = in_sizes[1] / 2;      // 1250000

    zero_kernel<<<(n + 255) / 256, 256>>>(ei, n);
    degcnt_kernel<<<(E + 255) / 256, 256>>>(ei, E);
    prep_kernel<<<(n + 255) / 256, 256>>>(x, n);
    scatter_kernel<<<(E + 255) / 256, 256>>>(ei, E);
    u_kernel<<<512, 256>>>(W1, b1, n);
    final_kernel<<<1, HID>>>(W2, b2, Wfc, bfc, out, n);
}